// round 3
// baseline (speedup 1.0000x reference)
#include <cuda_runtime.h>
#include <math.h>

// ---------------------------------------------------------------------------
// Radon backprojection, 2-kernel pipeline:
//   K1: transpose sino[B,A,P] -> sino_t[A,P,B] (float4 writes) + trig table
//   K2: 2 threads per pixel (angle-split halves), float4 accumulators,
//       shared-memory pairwise reduction. Doubles occupancy vs 1 thr/pixel.
// ---------------------------------------------------------------------------

#define MAX_A 2048
#define MAX_ELEMS (8 * 1024 * 1024)
#define PIX_PER_BLK 448   // 448 pixels * 2 angle-halves = 896 threads/block

__device__ float2 g_trig[MAX_A];        // (cos/dp, sin/dp)
__device__ float  g_c0;                 // -p0/dp
__device__ float  g_sino_t[MAX_ELEMS];  // [a][p][b], b innermost (BC==4 -> float4)

// K1: transpose + trig prep fused.
__global__ void radon_prep_transpose4_kernel(const float* __restrict__ sino,
                                             const float* __restrict__ thetas,
                                             const float* __restrict__ positions,
                                             int A, int P)
{
    int idx = blockIdx.x * blockDim.x + threadIdx.x;
    int AP = A * P;

    float p0  = positions[0];
    float dp  = positions[1] - positions[0];
    float inv = 1.0f / dp;

    if (idx < A) {
        float s, c;
        sincosf(thetas[idx], &s, &c);
        g_trig[idx] = make_float2(c * inv, s * inv);
    }
    if (idx == 0) g_c0 = -p0 * inv;

    if (idx < AP) {
        float4 v;
        v.x = __ldg(sino + idx);
        v.y = __ldg(sino + idx + AP);
        v.z = __ldg(sino + idx + 2 * AP);
        v.w = __ldg(sino + idx + 3 * AP);
        ((float4*)g_sino_t)[idx] = v;
    }
}

__global__ void radon_prep_transpose_kernel(const float* __restrict__ sino,
                                            const float* __restrict__ thetas,
                                            const float* __restrict__ positions,
                                            int BC, int A, int P)
{
    int idx = blockIdx.x * blockDim.x + threadIdx.x;
    int AP = A * P;

    float p0  = positions[0];
    float dp  = positions[1] - positions[0];
    float inv = 1.0f / dp;

    if (idx < A) {
        float s, c;
        sincosf(thetas[idx], &s, &c);
        g_trig[idx] = make_float2(c * inv, s * inv);
    }
    if (idx == 0) g_c0 = -p0 * inv;

    if (idx < AP) {
        for (int b = 0; b < BC; ++b)
            g_sino_t[idx * BC + b] = __ldg(sino + idx + b * AP);
    }
}

// K2 (BC==4): 2 threads per pixel, each sums half the angles; smem reduce.
__global__ void __launch_bounds__(2 * PIX_PER_BLK, 1)
radon_backproj4_kernel(float* __restrict__ out, int A, int P, int N, int NN)
{
    __shared__ float2 strig[MAX_A];
    __shared__ float4 sred[PIX_PER_BLK];

    int tid = threadIdx.x;                       // 0 .. 895
    for (int i = tid; i < A; i += 2 * PIX_PER_BLK) strig[i] = g_trig[i];
    __syncthreads();

    int tx = tid % PIX_PER_BLK;                  // pixel slot in block
    int h  = tid / PIX_PER_BLK;                  // angle half: 0 or 1
    int idx = blockIdx.x * PIX_PER_BLK + tx;
    bool live = (idx < NN);

    int x = idx % N;
    int y = idx / N;
    float half = 0.5f * (float)(N - 1);
    float cx = (float)x - half;
    float cy = half - (float)y;
    float c0 = g_c0;
    int   Pm2 = P - 2;

    int A2 = (A + 1) >> 1;
    int a_lo = h ? A2 : 0;
    int a_hi = h ? A  : A2;

    float4 acc = make_float4(0.f, 0.f, 0.f, 0.f);
    const float4* __restrict__ sino = (const float4*)g_sino_t;

    if (live) {
        #pragma unroll 4
        for (int a = a_lo; a < a_hi; ++a) {
            float2 tr = strig[a];
            float f  = fmaf(cx, tr.x, fmaf(cy, tr.y, c0));
            int   i0 = __float2int_rd(f);
            bool  valid = (i0 >= 0) && (i0 <= Pm2);
            int   i0c = min(max(i0, 0), Pm2);

            const float4* row = sino + a * P;
            float4 v0 = __ldg(row + i0c);
            float4 v1 = __ldg(row + i0c + 1);

            float w  = f - __int2float_rn(i0);
            float w1 = valid ? w        : 0.f;
            float w0 = valid ? 1.f - w  : 0.f;

            acc.x = fmaf(v0.x, w0, fmaf(v1.x, w1, acc.x));
            acc.y = fmaf(v0.y, w0, fmaf(v1.y, w1, acc.y));
            acc.z = fmaf(v0.z, w0, fmaf(v1.z, w1, acc.z));
            acc.w = fmaf(v0.w, w0, fmaf(v1.w, w1, acc.w));
        }
    }

    if (h == 1) sred[tx] = acc;
    __syncthreads();

    if (h == 0 && live) {
        float4 o = sred[tx];
        out[idx]          = acc.x + o.x;
        out[idx + NN]     = acc.y + o.y;
        out[idx + 2 * NN] = acc.z + o.z;
        out[idx + 3 * NN] = acc.w + o.w;
    }
}

// K2 generic BC fallback.
__global__ void radon_backproj_generic_kernel(float* __restrict__ out,
                                              int BC, int A, int P, int N, int NN)
{
    __shared__ float2 strig[MAX_A];
    for (int i = threadIdx.x; i < A; i += blockDim.x) strig[i] = g_trig[i];
    __syncthreads();

    int idx = blockIdx.x * blockDim.x + threadIdx.x;
    if (idx >= NN) return;

    int x = idx % N;
    int y = idx / N;
    float half = 0.5f * (float)(N - 1);
    float cx = (float)x - half;
    float cy = half - (float)y;
    float c0 = g_c0;
    int   Pm2 = P - 2;

    for (int b = 0; b < BC; ++b) {
        float acc = 0.f;
        for (int a = 0; a < A; ++a) {
            float2 tr = strig[a];
            float f  = fmaf(cx, tr.x, fmaf(cy, tr.y, c0));
            float fi = floorf(f);
            int   i0 = (int)fi;
            bool  valid = (i0 >= 0) && (i0 <= Pm2);
            int   i0c = min(max(i0, 0), Pm2);
            float v0 = g_sino_t[(a * P + i0c) * BC + b];
            float v1 = g_sino_t[(a * P + i0c + 1) * BC + b];
            float w  = f - fi;
            float w1 = valid ? w       : 0.f;
            float w0 = valid ? 1.f - w : 0.f;
            acc = fmaf(v0, w0, fmaf(v1, w1, acc));
        }
        out[b * NN + idx] = acc;
    }
}

extern "C" void kernel_launch(void* const* d_in, const int* in_sizes, int n_in,
                              void* d_out, int out_size)
{
    const float* sino      = (const float*)d_in[0];
    const float* thetas    = (const float*)d_in[1];
    const float* positions = (const float*)d_in[2];

    int A  = in_sizes[1];
    int P  = in_sizes[2];
    int BC = in_sizes[0] / (A * P);
    int N  = (int)(sqrt((double)(out_size / BC)) + 0.5);
    int NN = N * N;
    float* out = (float*)d_out;

    int AP = A * P;
    if (BC == 4) {
        radon_prep_transpose4_kernel<<<(AP + 255) / 256, 256>>>(sino, thetas, positions, A, P);
        int blocks = (NN + PIX_PER_BLK - 1) / PIX_PER_BLK;   // 147 for N=256
        radon_backproj4_kernel<<<blocks, 2 * PIX_PER_BLK>>>(out, A, P, N, NN);
    } else {
        radon_prep_transpose_kernel<<<(AP + 255) / 256, 256>>>(sino, thetas, positions, BC, A, P);
        radon_backproj_generic_kernel<<<(NN + 255) / 256, 256>>>(out, BC, A, P, N, NN);
    }
}

// round 4
// speedup vs baseline: 1.5111x; 1.5111x over previous
#include <cuda_runtime.h>
#include <math.h>

// ---------------------------------------------------------------------------
// Radon backprojection:
//   K1: transpose sino[B,A,P] -> sino_t[A,P,B] (+trig table, + zero d_out)
//   K2: grid-level angle split: even blocks sum angles [0,A/2), odd [A/2,A),
//       identical R2 loop body, epilogue RED.ADD into pre-zeroed output.
// ---------------------------------------------------------------------------

#define MAX_A 2048
#define MAX_ELEMS (8 * 1024 * 1024)
#define PIX_PER_BLK 448

__device__ float2 g_trig[MAX_A];        // (cos/dp, sin/dp)
__device__ float  g_c0;                 // -p0/dp
__device__ float  g_sino_t[MAX_ELEMS];  // [a][p][b], b innermost

// K1: transpose + trig prep + output zero-init, all fused.
__global__ void radon_prep_transpose4_kernel(const float* __restrict__ sino,
                                             const float* __restrict__ thetas,
                                             const float* __restrict__ positions,
                                             float4* __restrict__ out4,
                                             int A, int P, int NOUT4)
{
    int idx = blockIdx.x * blockDim.x + threadIdx.x;
    int AP = A * P;

    float p0  = positions[0];
    float dp  = positions[1] - positions[0];
    float inv = 1.0f / dp;

    if (idx < A) {
        float s, c;
        sincosf(thetas[idx], &s, &c);
        g_trig[idx] = make_float2(c * inv, s * inv);
    }
    if (idx == 0) g_c0 = -p0 * inv;

    if (idx < AP) {
        float4 v;
        v.x = __ldg(sino + idx);
        v.y = __ldg(sino + idx + AP);
        v.z = __ldg(sino + idx + 2 * AP);
        v.w = __ldg(sino + idx + 3 * AP);
        ((float4*)g_sino_t)[idx] = v;
    }
    if (idx < NOUT4)
        out4[idx] = make_float4(0.f, 0.f, 0.f, 0.f);
}

__global__ void radon_prep_transpose_kernel(const float* __restrict__ sino,
                                            const float* __restrict__ thetas,
                                            const float* __restrict__ positions,
                                            int BC, int A, int P)
{
    int idx = blockIdx.x * blockDim.x + threadIdx.x;
    int AP = A * P;

    float p0  = positions[0];
    float dp  = positions[1] - positions[0];
    float inv = 1.0f / dp;

    if (idx < A) {
        float s, c;
        sincosf(thetas[idx], &s, &c);
        g_trig[idx] = make_float2(c * inv, s * inv);
    }
    if (idx == 0) g_c0 = -p0 * inv;

    if (idx < AP) {
        for (int b = 0; b < BC; ++b)
            g_sino_t[idx * BC + b] = __ldg(sino + idx + b * AP);
    }
}

// K2 (BC==4): block-level angle split. Even blocks: first half of angles,
// odd blocks: second half. Loop body identical to the proven R2 kernel.
__global__ void __launch_bounds__(PIX_PER_BLK, 2)
radon_backproj4_kernel(float* __restrict__ out, int A, int P, int N, int NN)
{
    __shared__ float2 strig[MAX_A];
    for (int i = threadIdx.x; i < A; i += blockDim.x) strig[i] = g_trig[i];
    __syncthreads();

    int h   = blockIdx.x & 1;
    int idx = (blockIdx.x >> 1) * PIX_PER_BLK + threadIdx.x;
    if (idx >= NN) return;

    int x = idx % N;
    int y = idx / N;
    float half = 0.5f * (float)(N - 1);
    float cx = (float)x - half;
    float cy = half - (float)y;
    float c0 = g_c0;
    int   Pm2 = P - 2;

    int A2   = (A + 1) >> 1;
    int a_lo = h ? A2 : 0;
    int a_hi = h ? A  : A2;

    float4 acc = make_float4(0.f, 0.f, 0.f, 0.f);
    const float4* __restrict__ sino = (const float4*)g_sino_t;

    #pragma unroll 4
    for (int a = a_lo; a < a_hi; ++a) {
        float2 tr = strig[a];
        float f  = fmaf(cx, tr.x, fmaf(cy, tr.y, c0));
        float fi = floorf(f);
        int   i0 = (int)fi;
        bool  valid = (i0 >= 0) && (i0 <= Pm2);
        int   i0c = min(max(i0, 0), Pm2);

        const float4* row = sino + a * P;
        float4 v0 = __ldg(row + i0c);
        float4 v1 = __ldg(row + i0c + 1);

        float w  = f - fi;
        float w1 = valid ? w        : 0.f;
        float w0 = valid ? 1.f - w  : 0.f;

        acc.x = fmaf(v0.x, w0, fmaf(v1.x, w1, acc.x));
        acc.y = fmaf(v0.y, w0, fmaf(v1.y, w1, acc.y));
        acc.z = fmaf(v0.z, w0, fmaf(v1.z, w1, acc.z));
        acc.w = fmaf(v0.w, w0, fmaf(v1.w, w1, acc.w));
    }

    atomicAdd(out + idx,          acc.x);
    atomicAdd(out + idx + NN,     acc.y);
    atomicAdd(out + idx + 2 * NN, acc.z);
    atomicAdd(out + idx + 3 * NN, acc.w);
}

// K2 generic BC fallback (single pass, no atomics).
__global__ void radon_backproj_generic_kernel(float* __restrict__ out,
                                              int BC, int A, int P, int N, int NN)
{
    __shared__ float2 strig[MAX_A];
    for (int i = threadIdx.x; i < A; i += blockDim.x) strig[i] = g_trig[i];
    __syncthreads();

    int idx = blockIdx.x * blockDim.x + threadIdx.x;
    if (idx >= NN) return;

    int x = idx % N;
    int y = idx / N;
    float half = 0.5f * (float)(N - 1);
    float cx = (float)x - half;
    float cy = half - (float)y;
    float c0 = g_c0;
    int   Pm2 = P - 2;

    for (int b = 0; b < BC; ++b) {
        float acc = 0.f;
        for (int a = 0; a < A; ++a) {
            float2 tr = strig[a];
            float f  = fmaf(cx, tr.x, fmaf(cy, tr.y, c0));
            float fi = floorf(f);
            int   i0 = (int)fi;
            bool  valid = (i0 >= 0) && (i0 <= Pm2);
            int   i0c = min(max(i0, 0), Pm2);
            float v0 = g_sino_t[(a * P + i0c) * BC + b];
            float v1 = g_sino_t[(a * P + i0c + 1) * BC + b];
            float w  = f - fi;
            float w1 = valid ? w       : 0.f;
            float w0 = valid ? 1.f - w : 0.f;
            acc = fmaf(v0, w0, fmaf(v1, w1, acc));
        }
        out[b * NN + idx] = acc;
    }
}

extern "C" void kernel_launch(void* const* d_in, const int* in_sizes, int n_in,
                              void* d_out, int out_size)
{
    const float* sino      = (const float*)d_in[0];
    const float* thetas    = (const float*)d_in[1];
    const float* positions = (const float*)d_in[2];

    int A  = in_sizes[1];
    int P  = in_sizes[2];
    int BC = in_sizes[0] / (A * P);
    int N  = (int)(sqrt((double)(out_size / BC)) + 0.5);
    int NN = N * N;
    float* out = (float*)d_out;

    int AP = A * P;
    if (BC == 4) {
        int NOUT4 = (NN * 4) / 4;                       // float4 count of output
        int prep_elems = AP > NOUT4 ? AP : NOUT4;
        radon_prep_transpose4_kernel<<<(prep_elems + 255) / 256, 256>>>(
            sino, thetas, positions, (float4*)out, A, P, NOUT4);

        int stripes = (NN + PIX_PER_BLK - 1) / PIX_PER_BLK;  // 147 for N=256
        radon_backproj4_kernel<<<2 * stripes, PIX_PER_BLK>>>(out, A, P, N, NN);
    } else {
        radon_prep_transpose_kernel<<<(AP + 255) / 256, 256>>>(sino, thetas, positions, BC, A, P);
        radon_backproj_generic_kernel<<<(NN + 255) / 256, 256>>>(out, BC, A, P, N, NN);
    }
}